// round 1
// baseline (speedup 1.0000x reference)
#include <cuda_runtime.h>
#include <math.h>

#define BATCH 4
#define SEQ   2048
#define DM    1024
#define NH    16
#define DH    64
#define MROWS (BATCH*SEQ)   // 8192

// Scratch (static __device__ globals: allowed; no runtime allocation)
__device__ float g_qh[(size_t)BATCH*NH*SEQ*DH];   // [B,H,S,dh]
__device__ float g_kh[(size_t)BATCH*NH*SEQ*DH];
__device__ float g_vh[(size_t)BATCH*NH*SEQ*DH];
__device__ float g_ao[(size_t)MROWS*DM];          // [B*S, D]

// ---------------------------------------------------------------------------
// SGEMM: C[M,N] = A[M,K] @ W[K,N] + bias[N], M=8192, N=K=1024, fp32.
// 128x128 block tile, BK=8, 256 threads, 8x8 per thread.
// HEAD_OUT: remap output to [B,H,S,dh] (for Q/K/V projections).
// ---------------------------------------------------------------------------
template<bool HEAD_OUT>
__global__ __launch_bounds__(256) void sgemm_kernel(
    const float* __restrict__ A, const float* __restrict__ W,
    const float* __restrict__ bias, float* __restrict__ C)
{
    __shared__ float As[8][128];
    __shared__ float Bs[8][128];

    const int tid = threadIdx.x;
    const int bx = blockIdx.x, by = blockIdx.y;
    const int a_row = tid >> 1;              // 0..127
    const int a_col = (tid & 1) << 2;        // 0 or 4
    const int b_row = tid >> 5;              // 0..7
    const int b_col = (tid & 31) << 2;       // 0..124
    const int tx = tid & 15, ty = tid >> 4;

    const float* Aptr = A + (size_t)(by * 128 + a_row) * DM + a_col;
    const float* Wptr = W + (size_t)b_row * DM + bx * 128 + b_col;

    float acc[8][8];
    #pragma unroll
    for (int i = 0; i < 8; i++)
        #pragma unroll
        for (int j = 0; j < 8; j++) acc[i][j] = 0.f;

    for (int k0 = 0; k0 < DM; k0 += 8) {
        float4 av = *(const float4*)(Aptr + k0);
        float4 bv = *(const float4*)(Wptr + (size_t)k0 * DM);
        As[a_col + 0][a_row] = av.x;
        As[a_col + 1][a_row] = av.y;
        As[a_col + 2][a_row] = av.z;
        As[a_col + 3][a_row] = av.w;
        *(float4*)(&Bs[b_row][b_col]) = bv;
        __syncthreads();

        #pragma unroll
        for (int kk = 0; kk < 8; kk++) {
            float ra[8], rb[8];
            *(float4*)(ra)     = *(const float4*)(&As[kk][ty * 8]);
            *(float4*)(ra + 4) = *(const float4*)(&As[kk][ty * 8 + 4]);
            *(float4*)(rb)     = *(const float4*)(&Bs[kk][tx * 8]);
            *(float4*)(rb + 4) = *(const float4*)(&Bs[kk][tx * 8 + 4]);
            #pragma unroll
            for (int i = 0; i < 8; i++)
                #pragma unroll
                for (int j = 0; j < 8; j++)
                    acc[i][j] = fmaf(ra[i], rb[j], acc[i][j]);
        }
        __syncthreads();
    }

    #pragma unroll
    for (int i = 0; i < 8; i++) {
        const int row = by * 128 + ty * 8 + i;
        #pragma unroll
        for (int j = 0; j < 8; j++) {
            const int col = bx * 128 + tx * 8 + j;
            const float val = acc[i][j] + bias[col];
            if (HEAD_OUT) {
                const int b = row >> 11;        // / SEQ
                const int s = row & (SEQ - 1);
                const int h = col >> 6;         // / DH
                const int d = col & (DH - 1);
                C[((size_t)(b * NH + h) * SEQ + s) * DH + d] = val;
            } else {
                C[(size_t)row * DM + col] = val;
            }
        }
    }
}

// ---------------------------------------------------------------------------
// Flash attention: per (b,h) online-softmax, BQ=64 q-rows per block,
// iterate 64-row K/V tiles. 256 threads; thread (ty,tx) owns a 4x4 tile.
// Output written directly in [B,S,D] layout (head-interleaved) for O-proj.
// ---------------------------------------------------------------------------
#define BQ   64
#define BKV  64
#define PADW 65
#define FLASH_SMEM_FLOATS (4 * BQ * PADW)

__global__ __launch_bounds__(256) void flash_kernel(float* __restrict__ out)
{
    extern __shared__ float sm[];
    float* Qs = sm;                       // [BQ][PADW]
    float* Ks = Qs + BQ * PADW;           // [BKV][PADW]
    float* Vs = Ks + BQ * PADW;           // [BKV][PADW]
    float* Ps = Vs + BQ * PADW;           // [BQ][PADW]

    const int tid = threadIdx.x;
    const int tx = tid & 15, ty = tid >> 4;
    const int bh = blockIdx.y;            // b*NH + h
    const int q0 = blockIdx.x * BQ;

    const float* Qg = g_qh + (size_t)bh * SEQ * DH;
    const float* Kg = g_kh + (size_t)bh * SEQ * DH;
    const float* Vg = g_vh + (size_t)bh * SEQ * DH;

    // Load Q tile (64x64) once
    for (int i = tid; i < BQ * 16; i += 256) {
        const int r = i >> 4, c = (i & 15) << 2;
        float4 v4 = *(const float4*)(Qg + (size_t)(q0 + r) * DH + c);
        Qs[r * PADW + c + 0] = v4.x;
        Qs[r * PADW + c + 1] = v4.y;
        Qs[r * PADW + c + 2] = v4.z;
        Qs[r * PADW + c + 3] = v4.w;
    }

    float m_i[4], l_i[4], o[4][4];
    #pragma unroll
    for (int i = 0; i < 4; i++) {
        m_i[i] = -3.0e38f;
        l_i[i] = 0.f;
        #pragma unroll
        for (int j = 0; j < 4; j++) o[i][j] = 0.f;
    }

    const float sc = 0.125f;   // 1/sqrt(64)

    for (int k0 = 0; k0 < SEQ; k0 += BKV) {
        __syncthreads();   // previous PV done (and Q load on first iter)
        for (int i = tid; i < BKV * 16; i += 256) {
            const int r = i >> 4, c = (i & 15) << 2;
            float4 kv = *(const float4*)(Kg + (size_t)(k0 + r) * DH + c);
            float4 vv = *(const float4*)(Vg + (size_t)(k0 + r) * DH + c);
            Ks[r * PADW + c + 0] = kv.x; Ks[r * PADW + c + 1] = kv.y;
            Ks[r * PADW + c + 2] = kv.z; Ks[r * PADW + c + 3] = kv.w;
            Vs[r * PADW + c + 0] = vv.x; Vs[r * PADW + c + 1] = vv.y;
            Vs[r * PADW + c + 2] = vv.z; Vs[r * PADW + c + 3] = vv.w;
        }
        __syncthreads();

        // S = Q K^T (4x4 tile per thread)
        float s[4][4];
        #pragma unroll
        for (int i = 0; i < 4; i++)
            #pragma unroll
            for (int j = 0; j < 4; j++) s[i][j] = 0.f;

        for (int d = 0; d < DH; d++) {
            float qf[4], kf[4];
            #pragma unroll
            for (int i = 0; i < 4; i++) qf[i] = Qs[(ty * 4 + i) * PADW + d];
            #pragma unroll
            for (int j = 0; j < 4; j++) kf[j] = Ks[(tx * 4 + j) * PADW + d];
            #pragma unroll
            for (int i = 0; i < 4; i++)
                #pragma unroll
                for (int j = 0; j < 4; j++)
                    s[i][j] = fmaf(qf[i], kf[j], s[i][j]);
        }

        // online softmax per row (16 tx-lanes collaborate per row)
        #pragma unroll
        for (int i = 0; i < 4; i++) {
            float mx = -3.0e38f;
            #pragma unroll
            for (int j = 0; j < 4; j++) {
                s[i][j] *= sc;
                mx = fmaxf(mx, s[i][j]);
            }
            #pragma unroll
            for (int off = 8; off >= 1; off >>= 1)
                mx = fmaxf(mx, __shfl_xor_sync(0xffffffffu, mx, off));

            const float mnew = fmaxf(m_i[i], mx);
            const float alpha = __expf(m_i[i] - mnew);
            float sum = 0.f;
            #pragma unroll
            for (int j = 0; j < 4; j++) {
                const float p = __expf(s[i][j] - mnew);
                s[i][j] = p;
                sum += p;
            }
            #pragma unroll
            for (int off = 8; off >= 1; off >>= 1)
                sum += __shfl_xor_sync(0xffffffffu, sum, off);

            l_i[i] = l_i[i] * alpha + sum;
            m_i[i] = mnew;
            #pragma unroll
            for (int j = 0; j < 4; j++) {
                o[i][j] *= alpha;
                Ps[(ty * 4 + i) * PADW + tx * 4 + j] = s[i][j];
            }
        }
        __syncthreads();

        // O += P @ V
        for (int kk = 0; kk < BKV; kk++) {
            float pv[4], vv[4];
            #pragma unroll
            for (int i = 0; i < 4; i++) pv[i] = Ps[(ty * 4 + i) * PADW + kk];
            #pragma unroll
            for (int j = 0; j < 4; j++) vv[j] = Vs[kk * PADW + tx * 4 + j];
            #pragma unroll
            for (int i = 0; i < 4; i++)
                #pragma unroll
                for (int j = 0; j < 4; j++)
                    o[i][j] = fmaf(pv[i], vv[j], o[i][j]);
        }
    }

    // normalize, write to [B,S,D]
    const int b = bh >> 4;       // / NH
    const int h = bh & 15;
    #pragma unroll
    for (int i = 0; i < 4; i++) {
        const int srow = q0 + ty * 4 + i;
        const float inv = 1.f / l_i[i];
        #pragma unroll
        for (int j = 0; j < 4; j++)
            out[((size_t)(b * SEQ + srow)) * DM + h * DH + tx * 4 + j] = o[i][j] * inv;
    }
}

// ---------------------------------------------------------------------------
extern "C" void kernel_launch(void* const* d_in, const int* in_sizes, int n_in,
                              void* d_out, int out_size)
{
    const float* v  = (const float*)d_in[0];
    const float* k  = (const float*)d_in[1];
    const float* q  = (const float*)d_in[2];
    const float* wq = (const float*)d_in[3];
    const float* bq = (const float*)d_in[4];
    const float* wk = (const float*)d_in[5];
    const float* bk = (const float*)d_in[6];
    const float* wv = (const float*)d_in[7];
    const float* bv = (const float*)d_in[8];
    const float* wo = (const float*)d_in[9];
    const float* bo = (const float*)d_in[10];
    float* out = (float*)d_out;

    float *qh, *kh, *vh, *ao;
    cudaGetSymbolAddress((void**)&qh, g_qh);
    cudaGetSymbolAddress((void**)&kh, g_kh);
    cudaGetSymbolAddress((void**)&vh, g_vh);
    cudaGetSymbolAddress((void**)&ao, g_ao);

    cudaFuncSetAttribute(flash_kernel,
                         cudaFuncAttributeMaxDynamicSharedMemorySize,
                         FLASH_SMEM_FLOATS * (int)sizeof(float));

    dim3 gproj(DM / 128, MROWS / 128);   // (8, 64)
    sgemm_kernel<true><<<gproj, 256>>>(q, wq, bq, qh);
    sgemm_kernel<true><<<gproj, 256>>>(k, wk, bk, kh);
    sgemm_kernel<true><<<gproj, 256>>>(v, wv, bv, vh);

    dim3 gattn(SEQ / BQ, BATCH * NH);    // (32, 64)
    flash_kernel<<<gattn, 256, FLASH_SMEM_FLOATS * sizeof(float)>>>(ao);

    sgemm_kernel<false><<<gproj, 256>>>(ao, wo, bo, out);
}

// round 4
// speedup vs baseline: 3.4272x; 3.4272x over previous
#include <cuda_runtime.h>
#include <cstdint>
#include <math.h>

#define BATCH 4
#define SEQ   2048
#define DM    1024
#define NH    16
#define DH    64
#define MROWS (BATCH*SEQ)   // 8192

// ---------------------------------------------------------------------------
// Scratch (__device__ globals; no runtime allocation)
// ---------------------------------------------------------------------------
__device__ float g_qh[(size_t)BATCH*NH*SEQ*DH];   // [B,H,S,dh]
__device__ float g_kh[(size_t)BATCH*NH*SEQ*DH];
__device__ float g_vh[(size_t)BATCH*NH*SEQ*DH];
__device__ float g_ao[(size_t)MROWS*DM];          // [B*S, D] (tf32-rounded)
__device__ float g_qc[(size_t)MROWS*DM];          // tf32-rounded input copies
__device__ float g_kc[(size_t)MROWS*DM];
__device__ float g_vc[(size_t)MROWS*DM];
__device__ float g_wt[4][(size_t)DM*DM];          // transposed + rounded weights

// ---------------------------------------------------------------------------
// Helpers
// ---------------------------------------------------------------------------
__device__ __forceinline__ uint32_t smem_u32(const void* p) {
    uint32_t a;
    asm("{ .reg .u64 t; cvta.to.shared.u64 t, %1; cvt.u32.u64 %0, t; }" : "=r"(a) : "l"(p));
    return a;
}
__device__ __forceinline__ void cp16(uint32_t dst, const void* src) {
    asm volatile("cp.async.cg.shared.global [%0], [%1], 16;\n" :: "r"(dst), "l"(src) : "memory");
}
__device__ __forceinline__ void cp_commit() { asm volatile("cp.async.commit_group;" ::: "memory"); }

__device__ __forceinline__ float tf32_rna(float x) {
    uint32_t u;
    asm("cvt.rna.tf32.f32 %0, %1;" : "=r"(u) : "f"(x));
    return __uint_as_float(u);
}
__device__ __forceinline__ uint32_t fbits(float x) { return __float_as_uint(x); }

// D = A(16x8,row) * B(8x8,col) + C   (tf32 operands, f32 accum)
__device__ __forceinline__ void mma8(float* d, const uint32_t* a, uint32_t b0, uint32_t b1) {
    asm volatile(
        "mma.sync.aligned.m16n8k8.row.col.f32.tf32.tf32.f32 "
        "{%0,%1,%2,%3}, {%4,%5,%6,%7}, {%8,%9}, {%0,%1,%2,%3};"
        : "+f"(d[0]), "+f"(d[1]), "+f"(d[2]), "+f"(d[3])
        : "r"(a[0]), "r"(a[1]), "r"(a[2]), "r"(a[3]), "r"(b0), "r"(b1));
}

// ---------------------------------------------------------------------------
// tf32 HMMA GEMM: C[8192,1024] = A @ Wt^T + bias
// A row-major [M,K] (rounded); Wt row-major [N,K] (rounded).
// Block 128x128, BK=32, 256 threads (8 warps, warp tile 32x64).
// ---------------------------------------------------------------------------
#define GPAD 36
#define GTILE (128*GPAD)          // floats per (A or B) tile = 4608
#define GBUF  (2*GTILE)           // floats per buffer (A+B)   = 9216
#define TCG_SMEM (2*GBUF*4)       // 73728 bytes

template<bool HEAD_OUT>
__global__ __launch_bounds__(256) void tc_gemm(
    const float* __restrict__ A, const float* __restrict__ Wt,
    const float* __restrict__ bias, float* __restrict__ C)
{
    extern __shared__ float smf[];
    const uint32_t sbase = smem_u32(smf);
    const int tid = threadIdx.x;
    const int lane = tid & 31, wid = tid >> 5;
    const int g = lane >> 2, t = lane & 3;
    const int wm = wid & 3, wn = wid >> 2;       // warp tile: rows wm*32, cols wn*64

    const int m0 = blockIdx.y * 128;
    const int n0 = blockIdx.x * 128;

    auto issue = [&](int kc, int buf) {
        const int kcol = kc * 32;
        const uint32_t base = sbase + (uint32_t)buf * GBUF * 4;
        #pragma unroll
        for (int i = tid; i < 1024; i += 256) {
            const int r = i >> 3, c4 = (i & 7) * 4;
            cp16(base + (uint32_t)(r * GPAD + c4) * 4, A + (size_t)(m0 + r) * DM + kcol + c4);
        }
        const uint32_t bb = base + GTILE * 4;
        #pragma unroll
        for (int i = tid; i < 1024; i += 256) {
            const int r = i >> 3, c4 = (i & 7) * 4;
            cp16(bb + (uint32_t)(r * GPAD + c4) * 4, Wt + (size_t)(n0 + r) * DM + kcol + c4);
        }
        cp_commit();
    };

    float acc[2][8][4];
    #pragma unroll
    for (int mf = 0; mf < 2; mf++)
        #pragma unroll
        for (int nf = 0; nf < 8; nf++)
            #pragma unroll
            for (int c = 0; c < 4; c++) acc[mf][nf][c] = 0.f;

    issue(0, 0);
    issue(1, 1);

    #pragma unroll 1
    for (int c = 0; c < 32; c++) {
        const int buf = c & 1;
        if (c + 1 < 32) asm volatile("cp.async.wait_group 1;" ::: "memory");
        else            asm volatile("cp.async.wait_group 0;" ::: "memory");
        __syncthreads();

        const float* as = smf + buf * GBUF;
        const float* bs = as + GTILE;
        #pragma unroll
        for (int kk = 0; kk < 4; kk++) {
            const int k = kk * 8 + t;
            uint32_t a[2][4];
            #pragma unroll
            for (int mf = 0; mf < 2; mf++) {
                const int r = wm * 32 + mf * 16 + g;
                a[mf][0] = fbits(as[r * GPAD + k]);
                a[mf][1] = fbits(as[(r + 8) * GPAD + k]);
                a[mf][2] = fbits(as[r * GPAD + k + 4]);
                a[mf][3] = fbits(as[(r + 8) * GPAD + k + 4]);
            }
            #pragma unroll
            for (int nf = 0; nf < 8; nf++) {
                const int n = wn * 64 + nf * 8 + g;
                const uint32_t b0 = fbits(bs[n * GPAD + k]);
                const uint32_t b1 = fbits(bs[n * GPAD + k + 4]);
                mma8(acc[0][nf], a[0], b0, b1);
                mma8(acc[1][nf], a[1], b0, b1);
            }
        }
        __syncthreads();
        if (c + 2 < 32) issue(c + 2, buf);
    }

    // Epilogue: direct stores (+bias)
    #pragma unroll
    for (int mf = 0; mf < 2; mf++) {
        #pragma unroll
        for (int nf = 0; nf < 8; nf++) {
            const int rl = m0 + wm * 32 + mf * 16 + g;
            const int cl = n0 + wn * 64 + nf * 8 + 2 * t;
            #pragma unroll
            for (int cc = 0; cc < 4; cc++) {
                const int row = rl + (cc >> 1) * 8;
                const int col = cl + (cc & 1);
                const float val = acc[mf][nf][cc] + bias[col];
                if (HEAD_OUT) {
                    const int b = row >> 11, s = row & (SEQ - 1);
                    const int h = col >> 6,  d = col & (DH - 1);
                    C[((size_t)(b * NH + h) * SEQ + s) * DH + d] = val;
                } else {
                    C[(size_t)row * DM + col] = val;
                }
            }
        }
    }
}

// ---------------------------------------------------------------------------
// RNA-round fp32 -> tf32 values (vectorized copy)
// ---------------------------------------------------------------------------
__global__ __launch_bounds__(256) void cvt_tf32_kernel(const float4* __restrict__ in,
                                                       float4* __restrict__ out)
{
    const size_t i = (size_t)blockIdx.x * blockDim.x + threadIdx.x;
    float4 v = in[i];
    v.x = tf32_rna(v.x); v.y = tf32_rna(v.y);
    v.z = tf32_rna(v.z); v.w = tf32_rna(v.w);
    out[i] = v;
}

// Transpose 1024x1024 + RNA-round: Wt[n][k] = rna(W[k][n])
__global__ __launch_bounds__(256) void transpose_cvt_kernel(const float* __restrict__ W,
                                                            float* __restrict__ Wt)
{
    __shared__ float tbuf[32][33];
    const int tx = threadIdx.x, ty = threadIdx.y;     // 32 x 8
    const int bx = blockIdx.x * 32, by = blockIdx.y * 32;
    #pragma unroll
    for (int j = 0; j < 32; j += 8)
        tbuf[ty + j][tx] = W[(size_t)(by + ty + j) * DM + bx + tx];
    __syncthreads();
    #pragma unroll
    for (int j = 0; j < 32; j += 8)
        Wt[(size_t)(bx + ty + j) * DM + by + tx] = tf32_rna(tbuf[tx][ty + j]);
}

// ---------------------------------------------------------------------------
// Flash attention on tf32 HMMA. 128 threads (4 warps); warp w owns q rows
// [w*16, w*16+16). BQ=64 q-rows per block, 64-row K/V tiles.
// ---------------------------------------------------------------------------
#define FPQ 68            // pad for Qs/Ks/Ps ([row][k] access)
#define FPV 72            // pad for Vs ([k][n] access)
#define FQ_OFF 0
#define FK_OFF (64*FPQ)
#define FP_OFF (2*64*FPQ)
#define FV_OFF (3*64*FPQ)
#define FLASH_SMEM ((3*64*FPQ + 64*FPV) * 4)   // 70656 bytes

__global__ __launch_bounds__(128) void flash_kernel(float* __restrict__ out)
{
    extern __shared__ float sm[];
    float* Qs = sm + FQ_OFF;
    float* Ks = sm + FK_OFF;
    float* Ps = sm + FP_OFF;
    float* Vs = sm + FV_OFF;

    const int tid = threadIdx.x;
    const int lane = tid & 31, w = tid >> 5;
    const int g = lane >> 2, t = lane & 3;
    const int bh = blockIdx.y;
    const int q0 = blockIdx.x * 64;

    const float* Qg = g_qh + (size_t)bh * SEQ * DH;
    const float* Kg = g_kh + (size_t)bh * SEQ * DH;
    const float* Vg = g_vh + (size_t)bh * SEQ * DH;

    // Load Q tile once (rounded to tf32)
    for (int i = tid; i < 64 * 16; i += 128) {
        const int r = i >> 4, c = (i & 15) << 2;
        float4 v4 = *(const float4*)(Qg + (size_t)(q0 + r) * DH + c);
        v4.x = tf32_rna(v4.x); v4.y = tf32_rna(v4.y);
        v4.z = tf32_rna(v4.z); v4.w = tf32_rna(v4.w);
        *(float4*)(Qs + r * FPQ + c) = v4;
    }

    float oacc[8][4];
    #pragma unroll
    for (int nf = 0; nf < 8; nf++)
        #pragma unroll
        for (int c = 0; c < 4; c++) oacc[nf][c] = 0.f;
    float m0r = -3.0e38f, m1r = -3.0e38f, l0 = 0.f, l1 = 0.f;

    const float sc = 0.125f;   // 1/sqrt(64)
    const int qrow_l = w * 16 + g;   // local A-frag row (and +8)

    #pragma unroll 1
    for (int k0 = 0; k0 < SEQ; k0 += 64) {
        __syncthreads();   // prior tile fully consumed
        for (int i = tid; i < 64 * 16; i += 128) {
            const int r = i >> 4, c = (i & 15) << 2;
            float4 kv = *(const float4*)(Kg + (size_t)(k0 + r) * DH + c);
            kv.x = tf32_rna(kv.x); kv.y = tf32_rna(kv.y);
            kv.z = tf32_rna(kv.z); kv.w = tf32_rna(kv.w);
            *(float4*)(Ks + r * FPQ + c) = kv;
            float4 vv = *(const float4*)(Vg + (size_t)(k0 + r) * DH + c);
            vv.x = tf32_rna(vv.x); vv.y = tf32_rna(vv.y);
            vv.z = tf32_rna(vv.z); vv.w = tf32_rna(vv.w);
            *(float4*)(Vs + r * FPV + c) = vv;
        }
        __syncthreads();

        // S = Q K^T : warp computes 16x64
        float sacc[8][4];
        #pragma unroll
        for (int nf = 0; nf < 8; nf++)
            #pragma unroll
            for (int c = 0; c < 4; c++) sacc[nf][c] = 0.f;

        #pragma unroll
        for (int kk = 0; kk < 8; kk++) {
            const int k = kk * 8 + t;
            uint32_t a[4];
            a[0] = fbits(Qs[qrow_l * FPQ + k]);
            a[1] = fbits(Qs[(qrow_l + 8) * FPQ + k]);
            a[2] = fbits(Qs[qrow_l * FPQ + k + 4]);
            a[3] = fbits(Qs[(qrow_l + 8) * FPQ + k + 4]);
            #pragma unroll
            for (int nf = 0; nf < 8; nf++) {
                const int n = nf * 8 + g;
                mma8(sacc[nf], a, fbits(Ks[n * FPQ + k]), fbits(Ks[n * FPQ + k + 4]));
            }
        }

        // Online softmax on fragments (2 rows per thread: qrow_l, qrow_l+8)
        float mx0 = -3.0e38f, mx1 = -3.0e38f;
        #pragma unroll
        for (int nf = 0; nf < 8; nf++) {
            sacc[nf][0] *= sc; sacc[nf][1] *= sc;
            sacc[nf][2] *= sc; sacc[nf][3] *= sc;
            mx0 = fmaxf(mx0, fmaxf(sacc[nf][0], sacc[nf][1]));
            mx1 = fmaxf(mx1, fmaxf(sacc[nf][2], sacc[nf][3]));
        }
        mx0 = fmaxf(mx0, __shfl_xor_sync(0xffffffffu, mx0, 1));
        mx0 = fmaxf(mx0, __shfl_xor_sync(0xffffffffu, mx0, 2));
        mx1 = fmaxf(mx1, __shfl_xor_sync(0xffffffffu, mx1, 1));
        mx1 = fmaxf(mx1, __shfl_xor_sync(0xffffffffu, mx1, 2));

        const float mn0 = fmaxf(m0r, mx0), mn1 = fmaxf(m1r, mx1);
        const float al0 = __expf(m0r - mn0), al1 = __expf(m1r - mn1);
        float s0 = 0.f, s1 = 0.f;
        #pragma unroll
        for (int nf = 0; nf < 8; nf++) {
            float p;
            p = __expf(sacc[nf][0] - mn0); sacc[nf][0] = p; s0 += p;
            p = __expf(sacc[nf][1] - mn0); sacc[nf][1] = p; s0 += p;
            p = __expf(sacc[nf][2] - mn1); sacc[nf][2] = p; s1 += p;
            p = __expf(sacc[nf][3] - mn1); sacc[nf][3] = p; s1 += p;
        }
        s0 += __shfl_xor_sync(0xffffffffu, s0, 1);
        s0 += __shfl_xor_sync(0xffffffffu, s0, 2);
        s1 += __shfl_xor_sync(0xffffffffu, s1, 1);
        s1 += __shfl_xor_sync(0xffffffffu, s1, 2);
        l0 = l0 * al0 + s0; m0r = mn0;
        l1 = l1 * al1 + s1; m1r = mn1;

        // Rescale O, stage P (rounded) in warp-private smem rows
        #pragma unroll
        for (int nf = 0; nf < 8; nf++) {
            oacc[nf][0] *= al0; oacc[nf][1] *= al0;
            oacc[nf][2] *= al1; oacc[nf][3] *= al1;
            const int pc = nf * 8 + 2 * t;
            Ps[qrow_l * FPQ + pc]           = tf32_rna(sacc[nf][0]);
            Ps[qrow_l * FPQ + pc + 1]       = tf32_rna(sacc[nf][1]);
            Ps[(qrow_l + 8) * FPQ + pc]     = tf32_rna(sacc[nf][2]);
            Ps[(qrow_l + 8) * FPQ + pc + 1] = tf32_rna(sacc[nf][3]);
        }
        __syncwarp();

        // O += P V : A = Ps rows (16x64), B = Vs (64x64, [k][n])
        #pragma unroll
        for (int kk = 0; kk < 8; kk++) {
            const int k = kk * 8 + t;
            uint32_t a[4];
            a[0] = fbits(Ps[qrow_l * FPQ + k]);
            a[1] = fbits(Ps[(qrow_l + 8) * FPQ + k]);
            a[2] = fbits(Ps[qrow_l * FPQ + k + 4]);
            a[3] = fbits(Ps[(qrow_l + 8) * FPQ + k + 4]);
            #pragma unroll
            for (int nf = 0; nf < 8; nf++) {
                const int n = nf * 8 + g;
                mma8(oacc[nf], a, fbits(Vs[k * FPV + n]), fbits(Vs[(k + 4) * FPV + n]));
            }
        }
    }

    // Normalize + write to [B,S,D] (rounded for tf32 O-projection)
    const int b = bh >> 4, h = bh & 15;
    const float inv0 = 1.f / l0, inv1 = 1.f / l1;
    const int qrow = q0 + qrow_l;
    #pragma unroll
    for (int nf = 0; nf < 8; nf++) {
        const int col = h * DH + nf * 8 + 2 * t;
        float* o0 = out + (size_t)(b * SEQ + qrow) * DM + col;
        float* o1 = out + (size_t)(b * SEQ + qrow + 8) * DM + col;
        o0[0] = tf32_rna(oacc[nf][0] * inv0);
        o0[1] = tf32_rna(oacc[nf][1] * inv0);
        o1[0] = tf32_rna(oacc[nf][2] * inv1);
        o1[1] = tf32_rna(oacc[nf][3] * inv1);
    }
}

// ---------------------------------------------------------------------------
extern "C" void kernel_launch(void* const* d_in, const int* in_sizes, int n_in,
                              void* d_out, int out_size)
{
    const float* v  = (const float*)d_in[0];
    const float* k  = (const float*)d_in[1];
    const float* q  = (const float*)d_in[2];
    const float* wq = (const float*)d_in[3];
    const float* bq = (const float*)d_in[4];
    const float* wk = (const float*)d_in[5];
    const float* bk = (const float*)d_in[6];
    const float* wv = (const float*)d_in[7];
    const float* bv = (const float*)d_in[8];
    const float* wo = (const float*)d_in[9];
    const float* bo = (const float*)d_in[10];
    float* out = (float*)d_out;

    float *qh, *kh, *vh, *ao, *qc, *kc, *vc, *wt;
    cudaGetSymbolAddress((void**)&qh, g_qh);
    cudaGetSymbolAddress((void**)&kh, g_kh);
    cudaGetSymbolAddress((void**)&vh, g_vh);
    cudaGetSymbolAddress((void**)&ao, g_ao);
    cudaGetSymbolAddress((void**)&qc, g_qc);
    cudaGetSymbolAddress((void**)&kc, g_kc);
    cudaGetSymbolAddress((void**)&vc, g_vc);
    cudaGetSymbolAddress((void**)&wt, g_wt);

    cudaFuncSetAttribute(flash_kernel, cudaFuncAttributeMaxDynamicSharedMemorySize, FLASH_SMEM);
    cudaFuncSetAttribute(tc_gemm<true>,  cudaFuncAttributeMaxDynamicSharedMemorySize, TCG_SMEM);
    cudaFuncSetAttribute(tc_gemm<false>, cudaFuncAttributeMaxDynamicSharedMemorySize, TCG_SMEM);

    // 1) Round inputs / transpose+round weights
    const int cvt_blocks = (MROWS * DM / 4) / 256;   // 8192
    cvt_tf32_kernel<<<cvt_blocks, 256>>>((const float4*)q, (float4*)qc);
    cvt_tf32_kernel<<<cvt_blocks, 256>>>((const float4*)k, (float4*)kc);
    cvt_tf32_kernel<<<cvt_blocks, 256>>>((const float4*)v, (float4*)vc);

    dim3 tgrid(DM / 32, DM / 32);
    dim3 tblk(32, 8);
    transpose_cvt_kernel<<<tgrid, tblk>>>(wq, wt + 0 * (size_t)DM * DM);
    transpose_cvt_kernel<<<tgrid, tblk>>>(wk, wt + 1 * (size_t)DM * DM);
    transpose_cvt_kernel<<<tgrid, tblk>>>(wv, wt + 2 * (size_t)DM * DM);
    transpose_cvt_kernel<<<tgrid, tblk>>>(wo, wt + 3 * (size_t)DM * DM);

    // 2) Projections (tf32 HMMA)
    dim3 gproj(DM / 128, MROWS / 128);   // (8, 64)
    tc_gemm<true><<<gproj, 256, TCG_SMEM>>>(qc, wt + 0 * (size_t)DM * DM, bq, qh);
    tc_gemm<true><<<gproj, 256, TCG_SMEM>>>(kc, wt + 1 * (size_t)DM * DM, bk, kh);
    tc_gemm<true><<<gproj, 256, TCG_SMEM>>>(vc, wt + 2 * (size_t)DM * DM, bv, vh);

    // 3) Attention (tf32 HMMA flash)
    dim3 gattn(SEQ / 64, BATCH * NH);    // (32, 64)
    flash_kernel<<<gattn, 128, FLASH_SMEM>>>(ao);

    // 4) Output projection (tf32 HMMA)
    tc_gemm<false><<<gproj, 256, TCG_SMEM>>>(ao, wt + 3 * (size_t)DM * DM, bo, out);
}